// round 8
// baseline (speedup 1.0000x reference)
#include <cuda_runtime.h>
#include <cuda_bf16.h>
#include <cstdint>
#include <cstddef>

// ===========================================================================
// MoE GemmaMLP on GB300 -- base sm_103 target: mma.sync.m16n8k16 bf16 +
// ldmatrix + cp.async. bf16x3 split (Ahi*Bhi + Ahi*Blo + Alo*Bhi), fp32 acc.
// R6: 512-thread CTAs (16 warps/SM) + M=256 tiles to hide latency and cut L2.
// ===========================================================================

#define NB   32
#define NS   256
#define NH   1024
#define NI   4096
#define NEXP 9
#define NTASK 96

// ---------------- scratch (static device globals; no allocation) -----------
__device__ __align__(128) __nv_bfloat16 g_xs_hi[(size_t)NB * NS * NH];
__device__ __align__(128) __nv_bfloat16 g_xs_lo[(size_t)NB * NS * NH];
__device__ __align__(128) __nv_bfloat16 g_gT_hi[(size_t)NEXP * NI * NH];
__device__ __align__(128) __nv_bfloat16 g_gT_lo[(size_t)NEXP * NI * NH];
__device__ __align__(128) __nv_bfloat16 g_uT_hi[(size_t)NEXP * NI * NH];
__device__ __align__(128) __nv_bfloat16 g_uT_lo[(size_t)NEXP * NI * NH];
__device__ __align__(128) __nv_bfloat16 g_dT_hi[(size_t)NEXP * NH * NI];
__device__ __align__(128) __nv_bfloat16 g_dT_lo[(size_t)NEXP * NH * NI];
__device__ __align__(128) __nv_bfloat16 g_h_hi[(size_t)NTASK * NS * NI];
__device__ __align__(128) __nv_bfloat16 g_h_lo[(size_t)NTASK * NS * NI];
__device__ int   g_texp[NTASK];
__device__ float g_twgt[NTASK];
__device__ int   g_tsched[NTASK];

// ---------------- asm helpers ----------------------------------------------
__device__ __forceinline__ uint32_t smem_u32(const void* p) {
    uint32_t a;
    asm("{ .reg .u64 t; cvta.to.shared.u64 t, %1; cvt.u32.u64 %0, t; }"
        : "=r"(a) : "l"(p));
    return a;
}

__device__ __forceinline__ void cp16(uint32_t dst, const void* src) {
    asm volatile("cp.async.cg.shared.global [%0], [%1], 16;"
                 :: "r"(dst), "l"(src));
}
#define CP_COMMIT() asm volatile("cp.async.commit_group;" ::: "memory")
#define CP_WAIT1()  asm volatile("cp.async.wait_group 1;" ::: "memory")

#define LDM4(r0, r1, r2, r3, addr) \
    asm volatile("ldmatrix.sync.aligned.m8n8.x4.shared.b16 {%0,%1,%2,%3}, [%4];" \
                 : "=r"(r0), "=r"(r1), "=r"(r2), "=r"(r3) : "r"(addr))

#define MMA(d, a, b0, b1) \
    asm volatile("mma.sync.aligned.m16n8k16.row.col.f32.bf16.bf16.f32 " \
                 "{%0,%1,%2,%3}, {%4,%5,%6,%7}, {%8,%9}, {%0,%1,%2,%3};" \
                 : "+f"((d)[0]), "+f"((d)[1]), "+f"((d)[2]), "+f"((d)[3]) \
                 : "r"((a)[0]), "r"((a)[1]), "r"((a)[2]), "r"((a)[3]), \
                   "r"(b0), "r"(b1))

__device__ __forceinline__ float gelu_tanh(float g) {
    float z  = 0.7978845608028654f * (g + 0.044715f * g * g * g);
    float t  = __expf(-2.0f * fabsf(z));
    float th = (1.0f - t) / (1.0f + t);
    th = copysignf(th, z);
    return 0.5f * g * (1.0f + th);
}

// ---------------- routing ---------------------------------------------------
__global__ void k_route(const float* __restrict__ logits) {
    int b = threadIdx.x;
    if (b < NB) {
        float p[8];
        float mx = -1e30f;
        for (int e = 0; e < 8; e++) { p[e] = logits[b * 8 + e]; mx = fmaxf(mx, p[e]); }
        for (int e = 0; e < 8; e++) p[e] = __expf(p[e] - mx);
        int a1 = 0;
        for (int e = 1; e < 8; e++) if (p[e] > p[a1]) a1 = e;
        int a2 = (a1 == 0) ? 1 : 0;
        for (int e = 0; e < 8; e++) if (e != a1 && p[e] > p[a2]) a2 = e;
        float t = p[a1] + p[a2];
        g_texp[b * 3 + 0] = a1; g_twgt[b * 3 + 0] = p[a1] / t;
        g_texp[b * 3 + 1] = a2; g_twgt[b * 3 + 1] = p[a2] / t;
        g_texp[b * 3 + 2] = 8;  g_twgt[b * 3 + 2] = 1.0f;
    }
    __syncthreads();
    if (threadIdx.x == 0) {
        int pos = 0;
        for (int e = 0; e < NEXP; e++)
            for (int t = 0; t < NTASK; t++)
                if (g_texp[t] == e) g_tsched[pos++] = t;
    }
}

// ---------------- pack x ----------------------------------------------------
__global__ void k_pack_x(const float* __restrict__ x) {
    size_t i = (size_t)blockIdx.x * 256 + threadIdx.x;
    if (i < (size_t)NB * NS * NH) {
        float v = x[i];
        __nv_bfloat16 hi = __float2bfloat16(v);
        g_xs_hi[i] = hi;
        g_xs_lo[i] = __float2bfloat16(v - __bfloat162float(hi));
    }
}

// ---------------- transpose+split gate/up: [e][h][i] -> [e][i][h] ------------
__global__ void k_tr_gu(const float* __restrict__ sg, const float* __restrict__ shg,
                        const float* __restrict__ su, const float* __restrict__ shu) {
    __shared__ float tile[32][33];
    int z = blockIdx.z, which = z / NEXP, e = z % NEXP;
    size_t off = (size_t)e * NH * NI;
    const float* src;
    __nv_bfloat16 *dhi, *dlo;
    if (which == 0) { src = (e < 8) ? sg + off : shg; dhi = g_gT_hi + off; dlo = g_gT_lo + off; }
    else            { src = (e < 8) ? su + off : shu; dhi = g_uT_hi + off; dlo = g_uT_lo + off; }
    int i0 = blockIdx.x * 32, h0 = blockIdx.y * 32;
    int tx = threadIdx.x, ty = threadIdx.y;
#pragma unroll
    for (int k = 0; k < 4; k++)
        tile[ty + k * 8][tx] = src[(size_t)(h0 + ty + k * 8) * NI + i0 + tx];
    __syncthreads();
#pragma unroll
    for (int k = 0; k < 4; k++) {
        int ir = i0 + ty + k * 8;
        float v = tile[tx][ty + k * 8];
        __nv_bfloat16 hi = __float2bfloat16(v);
        dhi[(size_t)ir * NH + h0 + tx] = hi;
        dlo[(size_t)ir * NH + h0 + tx] = __float2bfloat16(v - __bfloat162float(hi));
    }
}

// ---------------- transpose+split down: [e][i][h] -> [e][h][i] ---------------
__global__ void k_tr_dn(const float* __restrict__ sd, const float* __restrict__ shd) {
    __shared__ float tile[32][33];
    int e = blockIdx.z;
    size_t off = (size_t)e * NI * NH;
    const float* src = (e < 8) ? sd + off : shd;
    __nv_bfloat16* dhi = g_dT_hi + off;
    __nv_bfloat16* dlo = g_dT_lo + off;
    int h0 = blockIdx.x * 32, i0 = blockIdx.y * 32;
    int tx = threadIdx.x, ty = threadIdx.y;
#pragma unroll
    for (int k = 0; k < 4; k++)
        tile[ty + k * 8][tx] = src[(size_t)(i0 + ty + k * 8) * NH + h0 + tx];
    __syncthreads();
#pragma unroll
    for (int k = 0; k < 4; k++) {
        int hr = h0 + ty + k * 8;
        float v = tile[tx][ty + k * 8];
        __nv_bfloat16 hi = __float2bfloat16(v);
        dhi[(size_t)hr * NI + i0 + tx] = hi;
        dlo[(size_t)hr * NI + i0 + tx] = __float2bfloat16(v - __bfloat162float(hi));
    }
}

// ===========================================================================
// GEMM1: h = w * gelu(x@G) * (x@U)
//   CTA tile 256(M) x 64(N) dual (gate & up), 512 threads (16 warps),
//   warp tile 32x32 dual, BK=32, 3 cp.async stages.
//   grid: task(96) x n(64); bid = p*64 + n
// SMEM rows padded to 80B (conflict-free for ldmatrix 8-row groups).
// ===========================================================================
#define ROWB 80
#define G1_STAGE (256 * ROWB + 128 * ROWB)           // A(256) + BG(64) + BU(64)
#define G1_SMEM  (3 * G1_STAGE)                      // 92160
#define G1_CHUNKS 96                                 // 3 passes x 32

__device__ __forceinline__ void g1_load(uint32_t sbase, int stage, int tid,
                                        const __nv_bfloat16* A,
                                        const __nv_bfloat16* BG,
                                        const __nv_bfloat16* BU) {
    uint32_t s = sbase + stage * G1_STAGE;
#pragma unroll
    for (int q = 0; q < 3; q++) {
        int t = tid + q * 512;                       // 0..1535
        if (t < 1024) {
            int r = t >> 2, j = t & 3;
            cp16(s + r * ROWB + j * 16, (const char*)(A + (size_t)r * NH) + j * 16);
        } else if (t < 1280) {
            int tt = t - 1024, r = tt >> 2, j = tt & 3;
            cp16(s + 256 * ROWB + r * ROWB + j * 16,
                 (const char*)(BG + (size_t)r * NH) + j * 16);
        } else {
            int tt = t - 1280, r = tt >> 2, j = tt & 3;
            cp16(s + 320 * ROWB + r * ROWB + j * 16,
                 (const char*)(BU + (size_t)r * NH) + j * 16);
        }
    }
}

__device__ __forceinline__ void g1_ptrs(int c, int batch, int e, int n0,
                                        const __nv_bfloat16*& A,
                                        const __nv_bfloat16*& BG,
                                        const __nv_bfloat16*& BU) {
    int pass = c >> 5, kc = c & 31;
    A  = (pass < 2 ? g_xs_hi : g_xs_lo) + ((size_t)batch * NS) * NH + kc * 32;
    BG = (pass == 1 ? g_gT_lo : g_gT_hi) + ((size_t)e * NI + n0) * NH + kc * 32;
    BU = (pass == 1 ? g_uT_lo : g_uT_hi) + ((size_t)e * NI + n0) * NH + kc * 32;
}

__global__ __launch_bounds__(512, 1) void k_gemm1() {
    extern __shared__ char smem[];
    const uint32_t sbase = smem_u32(smem);
    const int tid  = threadIdx.x;
    const int lane = tid & 31;
    const int wid  = tid >> 5;
    const int mb   = (wid >> 1) * 32;     // 8 m-positions (0..224)
    const int nb   = (wid & 1) * 32;      // 2 n-positions

    int bid = blockIdx.x;
    int p   = bid >> 6;
    int n   = bid & 63;
    int task  = g_tsched[p];
    int batch = task / 3;
    int e     = g_texp[task];
    int n0 = n * 64;

    float accg[2][4][4] = {}, accu[2][4][4] = {};

    const __nv_bfloat16 *A, *BG, *BU;
    g1_ptrs(0, batch, e, n0, A, BG, BU);
    g1_load(sbase, 0, tid, A, BG, BU);
    CP_COMMIT();
    g1_ptrs(1, batch, e, n0, A, BG, BU);
    g1_load(sbase, 1, tid, A, BG, BU);
    CP_COMMIT();

    const int rsel = lane & 15;
    const int ksel = (lane >> 4) & 1;

    for (int c = 0; c < G1_CHUNKS; c++) {
        CP_WAIT1();
        __syncthreads();
        {
            uint32_t sa = sbase + (c % 3) * G1_STAGE;
            uint32_t sg = sa + 256 * ROWB;
            uint32_t su = sa + 320 * ROWB;
#pragma unroll
            for (int k16 = 0; k16 < 2; k16++) {
                uint32_t kb = k16 * 32 + ksel * 16;
                uint32_t a[2][4];
#pragma unroll
                for (int mi = 0; mi < 2; mi++)
                    LDM4(a[mi][0], a[mi][1], a[mi][2], a[mi][3],
                         sa + (mb + mi * 16 + rsel) * ROWB + kb);
                uint32_t bg[4][2], bu[4][2];
#pragma unroll
                for (int bi = 0; bi < 2; bi++) {
                    uint32_t r0, r1, r2, r3;
                    LDM4(r0, r1, r2, r3, sg + (nb + bi * 16 + rsel) * ROWB + kb);
                    bg[bi * 2][0] = r0; bg[bi * 2][1] = r2;
                    bg[bi * 2 + 1][0] = r1; bg[bi * 2 + 1][1] = r3;
                    LDM4(r0, r1, r2, r3, su + (nb + bi * 16 + rsel) * ROWB + kb);
                    bu[bi * 2][0] = r0; bu[bi * 2][1] = r2;
                    bu[bi * 2 + 1][0] = r1; bu[bi * 2 + 1][1] = r3;
                }
#pragma unroll
                for (int mi = 0; mi < 2; mi++)
#pragma unroll
                    for (int ni = 0; ni < 4; ni++) {
                        MMA(accg[mi][ni], a[mi], bg[ni][0], bg[ni][1]);
                        MMA(accu[mi][ni], a[mi], bu[ni][0], bu[ni][1]);
                    }
            }
        }
        if (c + 2 < G1_CHUNKS) {
            g1_ptrs(c + 2, batch, e, n0, A, BG, BU);
            g1_load(sbase, (c + 2) % 3, tid, A, BG, BU);
        }
        CP_COMMIT();
    }

    // epilogue: v = w * gelu(g) * u, split to (hi, lo) bf16, store
    const float wt = g_twgt[task];
#pragma unroll
    for (int mi = 0; mi < 2; mi++)
#pragma unroll
        for (int ni = 0; ni < 4; ni++)
#pragma unroll
            for (int rp = 0; rp < 4; rp += 2) {
                int mrow = mb + mi * 16 + (lane >> 2) + (rp ? 8 : 0);
                int ncol = n0 + nb + ni * 8 + (lane & 3) * 2;
                float v0 = wt * gelu_tanh(accg[mi][ni][rp])     * accu[mi][ni][rp];
                float v1 = wt * gelu_tanh(accg[mi][ni][rp + 1]) * accu[mi][ni][rp + 1];
                __nv_bfloat16 h0 = __float2bfloat16(v0);
                __nv_bfloat16 h1 = __float2bfloat16(v1);
                __nv_bfloat16 l0 = __float2bfloat16(v0 - __bfloat162float(h0));
                __nv_bfloat16 l1 = __float2bfloat16(v1 - __bfloat162float(h1));
                size_t idx = ((size_t)task * NS + mrow) * NI + ncol;
                *reinterpret_cast<__nv_bfloat162*>(&g_h_hi[idx]) =
                    __nv_bfloat162(h0, h1);
                *reinterpret_cast<__nv_bfloat162*>(&g_h_lo[idx]) =
                    __nv_bfloat162(l0, l1);
            }
}

// ===========================================================================
// GEMM2: out[batch] = sum over {3 tasks x 3 passes} of h @ D^T
//   CTA tile 256(M) x 128(N), 512 threads (16 warps), warp 32x64,
//   BK=32, 3 stages.  grid: batch(32) x n(8); bid = batch*8 + n
// ===========================================================================
#define G2_STAGE (256 * ROWB + 128 * ROWB)           // 30720
#define G2_SMEM  (3 * G2_STAGE)                      // 92160
#define G2_CHUNKS 1152                               // 3 tasks x 3 passes x 128

__device__ __forceinline__ void g2_load(uint32_t sbase, int stage, int tid,
                                        const __nv_bfloat16* A,
                                        const __nv_bfloat16* B) {
    uint32_t s = sbase + stage * G2_STAGE;
#pragma unroll
    for (int q = 0; q < 3; q++) {
        int t = tid + q * 512;                       // 0..1535
        if (t < 1024) {
            int r = t >> 2, j = t & 3;
            cp16(s + r * ROWB + j * 16, (const char*)(A + (size_t)r * NI) + j * 16);
        } else {
            int tt = t - 1024, r = tt >> 2, j = tt & 3;
            cp16(s + 256 * ROWB + r * ROWB + j * 16,
                 (const char*)(B + (size_t)r * NI) + j * 16);
        }
    }
}

__device__ __forceinline__ void g2_ptrs(int c, int batch, int n0,
                                        const __nv_bfloat16*& A,
                                        const __nv_bfloat16*& B) {
    int ti = c / 384;
    int r  = c % 384;
    int pass = r >> 7;
    int kc   = r & 127;
    int task = batch * 3 + ti;
    int e    = g_texp[task];
    A = (pass < 2 ? g_h_hi : g_h_lo) + ((size_t)task * NS) * NI + kc * 32;
    B = (pass == 1 ? g_dT_lo : g_dT_hi) + ((size_t)e * NH + n0) * NI + kc * 32;
}

__global__ __launch_bounds__(512, 1) void k_gemm2(float* __restrict__ out) {
    extern __shared__ char smem[];
    const uint32_t sbase = smem_u32(smem);
    const int tid  = threadIdx.x;
    const int lane = tid & 31;
    const int wid  = tid >> 5;
    const int mb   = (wid >> 1) * 32;     // 8 m-positions
    const int nb   = (wid & 1) * 64;      // 2 n-positions

    int bid   = blockIdx.x;
    int batch = bid >> 3;
    int n     = bid & 7;
    int n0 = n * 128;

    float acc[2][8][4] = {};

    const __nv_bfloat16 *A, *B;
    g2_ptrs(0, batch, n0, A, B);
    g2_load(sbase, 0, tid, A, B);
    CP_COMMIT();
    g2_ptrs(1, batch, n0, A, B);
    g2_load(sbase, 1, tid, A, B);
    CP_COMMIT();

    const int rsel = lane & 15;
    const int ksel = (lane >> 4) & 1;

    for (int c = 0; c < G2_CHUNKS; c++) {
        CP_WAIT1();
        __syncthreads();
        {
            uint32_t sa = sbase + (c % 3) * G2_STAGE;
            uint32_t sb = sa + 256 * ROWB;
#pragma unroll
            for (int k16 = 0; k16 < 2; k16++) {
                uint32_t kb = k16 * 32 + ksel * 16;
                uint32_t a[2][4];
#pragma unroll
                for (int mi = 0; mi < 2; mi++)
                    LDM4(a[mi][0], a[mi][1], a[mi][2], a[mi][3],
                         sa + (mb + mi * 16 + rsel) * ROWB + kb);
                uint32_t bf[8][2];
#pragma unroll
                for (int bi = 0; bi < 4; bi++) {
                    uint32_t r0, r1, r2, r3;
                    LDM4(r0, r1, r2, r3, sb + (nb + bi * 16 + rsel) * ROWB + kb);
                    bf[bi * 2][0] = r0; bf[bi * 2][1] = r2;
                    bf[bi * 2 + 1][0] = r1; bf[bi * 2 + 1][1] = r3;
                }
#pragma unroll
                for (int mi = 0; mi < 2; mi++)
#pragma unroll
                    for (int ni = 0; ni < 8; ni++)
                        MMA(acc[mi][ni], a[mi], bf[ni][0], bf[ni][1]);
            }
        }
        if (c + 2 < G2_CHUNKS) {
            g2_ptrs(c + 2, batch, n0, A, B);
            g2_load(sbase, (c + 2) % 3, tid, A, B);
        }
        CP_COMMIT();
    }

    // epilogue: fp32 store (covers every output element exactly once)
#pragma unroll
    for (int mi = 0; mi < 2; mi++)
#pragma unroll
        for (int ni = 0; ni < 8; ni++)
#pragma unroll
            for (int rp = 0; rp < 4; rp += 2) {
                int mrow = mb + mi * 16 + (lane >> 2) + (rp ? 8 : 0);
                int ncol = n0 + nb + ni * 8 + (lane & 3) * 2;
                float2 v = make_float2(acc[mi][ni][rp], acc[mi][ni][rp + 1]);
                *reinterpret_cast<float2*>(
                    &out[((size_t)batch * NS + mrow) * NH + ncol]) = v;
            }
}

// ---------------- launch -----------------------------------------------------
extern "C" void kernel_launch(void* const* d_in, const int* in_sizes, int n_in,
                              void* d_out, int out_size) {
    const float* x      = (const float*)d_in[0];
    const float* logits = (const float*)d_in[1];
    const float* sg     = (const float*)d_in[2];
    const float* su     = (const float*)d_in[3];
    const float* sd     = (const float*)d_in[4];
    const float* shg    = (const float*)d_in[5];
    const float* shu    = (const float*)d_in[6];
    const float* shd    = (const float*)d_in[7];
    float* out = (float*)d_out;

    (void)cudaFuncSetAttribute(k_gemm1, cudaFuncAttributeMaxDynamicSharedMemorySize, G1_SMEM);
    (void)cudaFuncSetAttribute(k_gemm2, cudaFuncAttributeMaxDynamicSharedMemorySize, G2_SMEM);

    k_route<<<1, 128>>>(logits);
    k_pack_x<<<(NB * NS * NH) / 256, 256>>>(x);
    k_tr_gu<<<dim3(NI / 32, NH / 32, 2 * NEXP), dim3(32, 8)>>>(sg, shg, su, shu);
    k_tr_dn<<<dim3(NH / 32, NI / 32, NEXP), dim3(32, 8)>>>(sd, shd);
    k_gemm1<<<NTASK * 64, 512, G1_SMEM>>>();
    k_gemm2<<<NB * 8, 512, G2_SMEM>>>(out);
}

// round 10
// speedup vs baseline: 2.9174x; 2.9174x over previous
#include <cuda_runtime.h>
#include <cuda_fp16.h>
#include <cstdint>
#include <cstddef>

// ===========================================================================
// MoE GemmaMLP on GB300 -- base sm_103 target: mma.sync.m16n8k16 FP16 +
// ldmatrix + cp.async, fp32 accumulate, SINGLE PASS (fp16 11-bit mantissa
// gives ~2e-4 end-to-end rel err, 5x under the 1e-3 threshold; replaces the
// bf16x3-split => 3x fewer MACs on a saturated HMMA pipe).
// Config: proven R5 launch shape (256-thr CTAs, 128x64 / 128x128 tiles).
// ===========================================================================

#define NB   32
#define NS   256
#define NH   1024
#define NI   4096
#define NEXP 9
#define NTASK 96

// ---------------- scratch (static device globals; no allocation) -----------
__device__ __align__(128) __half g_xs[(size_t)NB * NS * NH];
__device__ __align__(128) __half g_gT[(size_t)NEXP * NI * NH];
__device__ __align__(128) __half g_uT[(size_t)NEXP * NI * NH];
__device__ __align__(128) __half g_dT[(size_t)NEXP * NH * NI];
__device__ __align__(128) __half g_h [(size_t)NTASK * NS * NI];
__device__ int   g_texp[NTASK];
__device__ float g_twgt[NTASK];
__device__ int   g_tsched[NTASK];

// ---------------- asm helpers ----------------------------------------------
__device__ __forceinline__ uint32_t smem_u32(const void* p) {
    uint32_t a;
    asm("{ .reg .u64 t; cvta.to.shared.u64 t, %1; cvt.u32.u64 %0, t; }"
        : "=r"(a) : "l"(p));
    return a;
}

__device__ __forceinline__ void cp16(uint32_t dst, const void* src) {
    asm volatile("cp.async.cg.shared.global [%0], [%1], 16;"
                 :: "r"(dst), "l"(src));
}
#define CP_COMMIT() asm volatile("cp.async.commit_group;" ::: "memory")
#define CP_WAIT1()  asm volatile("cp.async.wait_group 1;" ::: "memory")

#define LDM4(r0, r1, r2, r3, addr) \
    asm volatile("ldmatrix.sync.aligned.m8n8.x4.shared.b16 {%0,%1,%2,%3}, [%4];" \
                 : "=r"(r0), "=r"(r1), "=r"(r2), "=r"(r3) : "r"(addr))

#define MMA(d, a, b0, b1) \
    asm volatile("mma.sync.aligned.m16n8k16.row.col.f32.f16.f16.f32 " \
                 "{%0,%1,%2,%3}, {%4,%5,%6,%7}, {%8,%9}, {%0,%1,%2,%3};" \
                 : "+f"((d)[0]), "+f"((d)[1]), "+f"((d)[2]), "+f"((d)[3]) \
                 : "r"((a)[0]), "r"((a)[1]), "r"((a)[2]), "r"((a)[3]), \
                   "r"(b0), "r"(b1))

__device__ __forceinline__ float gelu_tanh(float g) {
    float z  = 0.7978845608028654f * (g + 0.044715f * g * g * g);
    float t  = __expf(-2.0f * fabsf(z));
    float th = (1.0f - t) / (1.0f + t);
    th = copysignf(th, z);
    return 0.5f * g * (1.0f + th);
}

// ---------------- routing ---------------------------------------------------
__global__ void k_route(const float* __restrict__ logits) {
    int b = threadIdx.x;
    if (b < NB) {
        float p[8];
        float mx = -1e30f;
        for (int e = 0; e < 8; e++) { p[e] = logits[b * 8 + e]; mx = fmaxf(mx, p[e]); }
        for (int e = 0; e < 8; e++) p[e] = __expf(p[e] - mx);
        int a1 = 0;
        for (int e = 1; e < 8; e++) if (p[e] > p[a1]) a1 = e;
        int a2 = (a1 == 0) ? 1 : 0;
        for (int e = 0; e < 8; e++) if (e != a1 && p[e] > p[a2]) a2 = e;
        float t = p[a1] + p[a2];
        g_texp[b * 3 + 0] = a1; g_twgt[b * 3 + 0] = p[a1] / t;
        g_texp[b * 3 + 1] = a2; g_twgt[b * 3 + 1] = p[a2] / t;
        g_texp[b * 3 + 2] = 8;  g_twgt[b * 3 + 2] = 1.0f;
    }
    __syncthreads();
    if (threadIdx.x == 0) {
        int pos = 0;
        for (int e = 0; e < NEXP; e++)
            for (int t = 0; t < NTASK; t++)
                if (g_texp[t] == e) g_tsched[pos++] = t;
    }
}

// ---------------- pack x: fp32 -> fp16 --------------------------------------
__global__ void k_pack_x(const float* __restrict__ x) {
    size_t i = (size_t)blockIdx.x * 256 + threadIdx.x;
    if (i < (size_t)NB * NS * NH)
        g_xs[i] = __float2half(x[i]);
}

// ---------------- transpose gate/up: [e][h][i] -> [e][i][h] fp16 -------------
__global__ void k_tr_gu(const float* __restrict__ sg, const float* __restrict__ shg,
                        const float* __restrict__ su, const float* __restrict__ shu) {
    __shared__ float tile[32][33];
    int z = blockIdx.z, which = z / NEXP, e = z % NEXP;
    size_t off = (size_t)e * NH * NI;
    const float* src;
    __half* dst;
    if (which == 0) { src = (e < 8) ? sg + off : shg; dst = g_gT + off; }
    else            { src = (e < 8) ? su + off : shu; dst = g_uT + off; }
    int i0 = blockIdx.x * 32, h0 = blockIdx.y * 32;
    int tx = threadIdx.x, ty = threadIdx.y;
#pragma unroll
    for (int k = 0; k < 4; k++)
        tile[ty + k * 8][tx] = src[(size_t)(h0 + ty + k * 8) * NI + i0 + tx];
    __syncthreads();
#pragma unroll
    for (int k = 0; k < 4; k++) {
        int ir = i0 + ty + k * 8;
        dst[(size_t)ir * NH + h0 + tx] = __float2half(tile[tx][ty + k * 8]);
    }
}

// ---------------- transpose down: [e][i][h] -> [e][h][i] fp16 ----------------
__global__ void k_tr_dn(const float* __restrict__ sd, const float* __restrict__ shd) {
    __shared__ float tile[32][33];
    int e = blockIdx.z;
    size_t off = (size_t)e * NI * NH;
    const float* src = (e < 8) ? sd + off : shd;
    __half* dst = g_dT + off;
    int h0 = blockIdx.x * 32, i0 = blockIdx.y * 32;
    int tx = threadIdx.x, ty = threadIdx.y;
#pragma unroll
    for (int k = 0; k < 4; k++)
        tile[ty + k * 8][tx] = src[(size_t)(i0 + ty + k * 8) * NH + h0 + tx];
    __syncthreads();
#pragma unroll
    for (int k = 0; k < 4; k++) {
        int hr = h0 + ty + k * 8;
        dst[(size_t)hr * NI + i0 + tx] = __float2half(tile[tx][ty + k * 8]);
    }
}

// ===========================================================================
// GEMM1: h = w * gelu(x@G) * (x@U)
//   CTA tile 128(M) x 64(N), dual output (gate & up), BK=32, 3 cp.async
//   stages, 256 threads. grid: task(96) x m(2) x n(64); bid = p*128 + m*64 + n
//   K-chunks: 32 (single fp16 pass over K=1024).
// SMEM rows padded to 80B (conflict-free for ldmatrix 8-row groups).
// ===========================================================================
#define ROWB 80
#define G1_STAGE (128 * ROWB + 64 * ROWB * 2)       // 20480
#define G1_SMEM  (3 * G1_STAGE)                      // 61440
#define G1_CHUNKS 32

__device__ __forceinline__ void g1_load(uint32_t sbase, int stage, int tid,
                                        const __half* A,
                                        const __half* BG,
                                        const __half* BU) {
    uint32_t s = sbase + stage * G1_STAGE;
#pragma unroll
    for (int q = 0; q < 4; q++) {
        int t = tid + q * 256;
        if (t < 512) {
            int r = t >> 2, j = t & 3;
            cp16(s + r * ROWB + j * 16, (const char*)(A + (size_t)r * NH) + j * 16);
        } else if (t < 768) {
            int tt = t - 512, r = tt >> 2, j = tt & 3;
            cp16(s + 128 * ROWB + r * ROWB + j * 16,
                 (const char*)(BG + (size_t)r * NH) + j * 16);
        } else {
            int tt = t - 768, r = tt >> 2, j = tt & 3;
            cp16(s + 192 * ROWB + r * ROWB + j * 16,
                 (const char*)(BU + (size_t)r * NH) + j * 16);
        }
    }
}

__device__ __forceinline__ void g1_ptrs(int c, int batch, int e, int m0, int n0,
                                        const __half*& A,
                                        const __half*& BG,
                                        const __half*& BU) {
    A  = g_xs + ((size_t)batch * NS + m0) * NH + c * 32;
    BG = g_gT + ((size_t)e * NI + n0) * NH + c * 32;
    BU = g_uT + ((size_t)e * NI + n0) * NH + c * 32;
}

__global__ __launch_bounds__(256, 1) void k_gemm1() {
    extern __shared__ char smem[];
    const uint32_t sbase = smem_u32(smem);
    const int tid  = threadIdx.x;
    const int lane = tid & 31;
    const int wid  = tid >> 5;
    const int mb   = (wid >> 1) * 32;     // warp m-offset within CTA tile
    const int nb   = (wid & 1) * 32;      // warp n-offset

    int bid = blockIdx.x;
    int p   = bid >> 7;
    int m   = (bid >> 6) & 1;
    int n   = bid & 63;
    int task  = g_tsched[p];
    int batch = task / 3;
    int e     = g_texp[task];
    int m0 = m * 128, n0 = n * 64;

    float accg[2][4][4] = {}, accu[2][4][4] = {};

    const __half *A, *BG, *BU;
    g1_ptrs(0, batch, e, m0, n0, A, BG, BU);
    g1_load(sbase, 0, tid, A, BG, BU);
    CP_COMMIT();
    g1_ptrs(1, batch, e, m0, n0, A, BG, BU);
    g1_load(sbase, 1, tid, A, BG, BU);
    CP_COMMIT();

    const int rsel = lane & 15;
    const int ksel = (lane >> 4) & 1;

    for (int c = 0; c < G1_CHUNKS; c++) {
        CP_WAIT1();
        __syncthreads();
        {
            uint32_t sa = sbase + (c % 3) * G1_STAGE;
            uint32_t sg = sa + 128 * ROWB;
            uint32_t su = sa + 192 * ROWB;
#pragma unroll
            for (int k16 = 0; k16 < 2; k16++) {
                uint32_t kb = k16 * 32 + ksel * 16;
                uint32_t a[2][4];
#pragma unroll
                for (int mi = 0; mi < 2; mi++)
                    LDM4(a[mi][0], a[mi][1], a[mi][2], a[mi][3],
                         sa + (mb + mi * 16 + rsel) * ROWB + kb);
                uint32_t bg[4][2], bu[4][2];
#pragma unroll
                for (int bi = 0; bi < 2; bi++) {
                    uint32_t r0, r1, r2, r3;
                    LDM4(r0, r1, r2, r3, sg + (nb + bi * 16 + rsel) * ROWB + kb);
                    bg[bi * 2][0] = r0; bg[bi * 2][1] = r2;
                    bg[bi * 2 + 1][0] = r1; bg[bi * 2 + 1][1] = r3;
                    LDM4(r0, r1, r2, r3, su + (nb + bi * 16 + rsel) * ROWB + kb);
                    bu[bi * 2][0] = r0; bu[bi * 2][1] = r2;
                    bu[bi * 2 + 1][0] = r1; bu[bi * 2 + 1][1] = r3;
                }
#pragma unroll
                for (int mi = 0; mi < 2; mi++)
#pragma unroll
                    for (int ni = 0; ni < 4; ni++) {
                        MMA(accg[mi][ni], a[mi], bg[ni][0], bg[ni][1]);
                        MMA(accu[mi][ni], a[mi], bu[ni][0], bu[ni][1]);
                    }
            }
        }
        if (c + 2 < G1_CHUNKS) {
            g1_ptrs(c + 2, batch, e, m0, n0, A, BG, BU);
            g1_load(sbase, (c + 2) % 3, tid, A, BG, BU);
        }
        CP_COMMIT();
    }

    // epilogue: v = w * gelu(g) * u -> fp16 store
    const float wt = g_twgt[task];
#pragma unroll
    for (int mi = 0; mi < 2; mi++)
#pragma unroll
        for (int ni = 0; ni < 4; ni++)
#pragma unroll
            for (int rp = 0; rp < 4; rp += 2) {
                int mrow = m0 + mb + mi * 16 + (lane >> 2) + (rp ? 8 : 0);
                int ncol = n0 + nb + ni * 8 + (lane & 3) * 2;
                float v0 = wt * gelu_tanh(accg[mi][ni][rp])     * accu[mi][ni][rp];
                float v1 = wt * gelu_tanh(accg[mi][ni][rp + 1]) * accu[mi][ni][rp + 1];
                size_t idx = ((size_t)task * NS + mrow) * NI + ncol;
                *reinterpret_cast<__half2*>(&g_h[idx]) =
                    __halves2half2(__float2half(v0), __float2half(v1));
            }
}

// ===========================================================================
// GEMM2: out[batch] = sum over {3 tasks} of h @ D^T  (single fp16 pass)
//   CTA tile 128(M) x 128(N), warp 32x64, BK=32, 3 stages, 256 threads.
//   grid: batch(32) x m(2) x n(8); bid = batch*16 + m*8 + n
//   K-chunks: 3 tasks x 128 = 384.
// ===========================================================================
#define G2_STAGE (128 * ROWB * 2)                    // 20480
#define G2_SMEM  (3 * G2_STAGE)                      // 61440
#define G2_CHUNKS 384

__device__ __forceinline__ void g2_load(uint32_t sbase, int stage, int tid,
                                        const __half* A,
                                        const __half* B) {
    uint32_t s = sbase + stage * G2_STAGE;
#pragma unroll
    for (int q = 0; q < 4; q++) {
        int t = tid + q * 256;
        if (t < 512) {
            int r = t >> 2, j = t & 3;
            cp16(s + r * ROWB + j * 16, (const char*)(A + (size_t)r * NI) + j * 16);
        } else {
            int tt = t - 512, r = tt >> 2, j = tt & 3;
            cp16(s + 128 * ROWB + r * ROWB + j * 16,
                 (const char*)(B + (size_t)r * NI) + j * 16);
        }
    }
}

__device__ __forceinline__ void g2_ptrs(int c, int batch, int m0, int n0,
                                        const __half*& A,
                                        const __half*& B) {
    int ti = c >> 7;            // 0..2
    int kc = c & 127;
    int task = batch * 3 + ti;
    int e    = g_texp[task];
    A = g_h  + ((size_t)task * NS + m0) * NI + kc * 32;
    B = g_dT + ((size_t)e * NH + n0) * NI + kc * 32;
}

__global__ __launch_bounds__(256, 1) void k_gemm2(float* __restrict__ out) {
    extern __shared__ char smem[];
    const uint32_t sbase = smem_u32(smem);
    const int tid  = threadIdx.x;
    const int lane = tid & 31;
    const int wid  = tid >> 5;
    const int mb   = (wid >> 1) * 32;
    const int nb   = (wid & 1) * 64;

    int bid   = blockIdx.x;
    int batch = bid >> 4;
    int m     = (bid >> 3) & 1;
    int n     = bid & 7;
    int m0 = m * 128, n0 = n * 128;

    float acc[2][8][4] = {};

    const __half *A, *B;
    g2_ptrs(0, batch, m0, n0, A, B);
    g2_load(sbase, 0, tid, A, B);
    CP_COMMIT();
    g2_ptrs(1, batch, m0, n0, A, B);
    g2_load(sbase, 1, tid, A, B);
    CP_COMMIT();

    const int rsel = lane & 15;
    const int ksel = (lane >> 4) & 1;

    for (int c = 0; c < G2_CHUNKS; c++) {
        CP_WAIT1();
        __syncthreads();
        {
            uint32_t sa = sbase + (c % 3) * G2_STAGE;
            uint32_t sb = sa + 128 * ROWB;
#pragma unroll
            for (int k16 = 0; k16 < 2; k16++) {
                uint32_t kb = k16 * 32 + ksel * 16;
                uint32_t a[2][4];
#pragma unroll
                for (int mi = 0; mi < 2; mi++)
                    LDM4(a[mi][0], a[mi][1], a[mi][2], a[mi][3],
                         sa + (mb + mi * 16 + rsel) * ROWB + kb);
                uint32_t bf[8][2];
#pragma unroll
                for (int bi = 0; bi < 4; bi++) {
                    uint32_t r0, r1, r2, r3;
                    LDM4(r0, r1, r2, r3, sb + (nb + bi * 16 + rsel) * ROWB + kb);
                    bf[bi * 2][0] = r0; bf[bi * 2][1] = r2;
                    bf[bi * 2 + 1][0] = r1; bf[bi * 2 + 1][1] = r3;
                }
#pragma unroll
                for (int mi = 0; mi < 2; mi++)
#pragma unroll
                    for (int ni = 0; ni < 8; ni++)
                        MMA(acc[mi][ni], a[mi], bf[ni][0], bf[ni][1]);
            }
        }
        if (c + 2 < G2_CHUNKS) {
            g2_ptrs(c + 2, batch, m0, n0, A, B);
            g2_load(sbase, (c + 2) % 3, tid, A, B);
        }
        CP_COMMIT();
    }

    // epilogue: fp32 store (covers every output element exactly once)
#pragma unroll
    for (int mi = 0; mi < 2; mi++)
#pragma unroll
        for (int ni = 0; ni < 8; ni++)
#pragma unroll
            for (int rp = 0; rp < 4; rp += 2) {
                int mrow = m0 + mb + mi * 16 + (lane >> 2) + (rp ? 8 : 0);
                int ncol = n0 + nb + ni * 8 + (lane & 3) * 2;
                float2 v = make_float2(acc[mi][ni][rp], acc[mi][ni][rp + 1]);
                *reinterpret_cast<float2*>(
                    &out[((size_t)batch * NS + mrow) * NH + ncol]) = v;
            }
}

// ---------------- launch -----------------------------------------------------
extern "C" void kernel_launch(void* const* d_in, const int* in_sizes, int n_in,
                              void* d_out, int out_size) {
    const float* x      = (const float*)d_in[0];
    const float* logits = (const float*)d_in[1];
    const float* sg     = (const float*)d_in[2];
    const float* su     = (const float*)d_in[3];
    const float* sd     = (const float*)d_in[4];
    const float* shg    = (const float*)d_in[5];
    const float* shu    = (const float*)d_in[6];
    const float* shd    = (const float*)d_in[7];
    float* out = (float*)d_out;

    (void)cudaFuncSetAttribute(k_gemm1, cudaFuncAttributeMaxDynamicSharedMemorySize, G1_SMEM);
    (void)cudaFuncSetAttribute(k_gemm2, cudaFuncAttributeMaxDynamicSharedMemorySize, G2_SMEM);

    k_route<<<1, 128>>>(logits);
    k_pack_x<<<(NB * NS * NH) / 256, 256>>>(x);
    k_tr_gu<<<dim3(NI / 32, NH / 32, 2 * NEXP), dim3(32, 8)>>>(sg, shg, su, shu);
    k_tr_dn<<<dim3(NH / 32, NI / 32, NEXP), dim3(32, 8)>>>(sd, shd);
    k_gemm1<<<NTASK * 2 * 64, 256, G1_SMEM>>>();
    k_gemm2<<<NB * 2 * 8, 256, G2_SMEM>>>(out);
}

// round 11
// speedup vs baseline: 3.2959x; 1.1298x over previous
#include <cuda_runtime.h>
#include <cuda_fp16.h>
#include <cstdint>
#include <cstddef>

// ===========================================================================
// MoE GemmaMLP on GB300 -- base sm_103 target: mma.sync.m16n8k16 FP16 +
// ldmatrix + cp.async, fp32 accumulate, single pass.
// R11: BK=64 per pipeline stage (half the barriers, same math order).
// ===========================================================================

#define NB   32
#define NS   256
#define NH   1024
#define NI   4096
#define NEXP 9
#define NTASK 96

// ---------------- scratch (static device globals; no allocation) -----------
__device__ __align__(128) __half g_xs[(size_t)NB * NS * NH];
__device__ __align__(128) __half g_gT[(size_t)NEXP * NI * NH];
__device__ __align__(128) __half g_uT[(size_t)NEXP * NI * NH];
__device__ __align__(128) __half g_dT[(size_t)NEXP * NH * NI];
__device__ __align__(128) __half g_h [(size_t)NTASK * NS * NI];
__device__ int   g_texp[NTASK];
__device__ float g_twgt[NTASK];
__device__ int   g_tsched[NTASK];

// ---------------- asm helpers ----------------------------------------------
__device__ __forceinline__ uint32_t smem_u32(const void* p) {
    uint32_t a;
    asm("{ .reg .u64 t; cvta.to.shared.u64 t, %1; cvt.u32.u64 %0, t; }"
        : "=r"(a) : "l"(p));
    return a;
}

__device__ __forceinline__ void cp16(uint32_t dst, const void* src) {
    asm volatile("cp.async.cg.shared.global [%0], [%1], 16;"
                 :: "r"(dst), "l"(src));
}
#define CP_COMMIT() asm volatile("cp.async.commit_group;" ::: "memory")
#define CP_WAIT1()  asm volatile("cp.async.wait_group 1;" ::: "memory")

#define LDM4(r0, r1, r2, r3, addr) \
    asm volatile("ldmatrix.sync.aligned.m8n8.x4.shared.b16 {%0,%1,%2,%3}, [%4];" \
                 : "=r"(r0), "=r"(r1), "=r"(r2), "=r"(r3) : "r"(addr))

#define MMA(d, a, b0, b1) \
    asm volatile("mma.sync.aligned.m16n8k16.row.col.f32.f16.f16.f32 " \
                 "{%0,%1,%2,%3}, {%4,%5,%6,%7}, {%8,%9}, {%0,%1,%2,%3};" \
                 : "+f"((d)[0]), "+f"((d)[1]), "+f"((d)[2]), "+f"((d)[3]) \
                 : "r"((a)[0]), "r"((a)[1]), "r"((a)[2]), "r"((a)[3]), \
                   "r"(b0), "r"(b1))

__device__ __forceinline__ float gelu_tanh(float g) {
    float z  = 0.7978845608028654f * (g + 0.044715f * g * g * g);
    float t  = __expf(-2.0f * fabsf(z));
    float th = (1.0f - t) / (1.0f + t);
    th = copysignf(th, z);
    return 0.5f * g * (1.0f + th);
}

// ---------------- routing ---------------------------------------------------
__global__ void k_route(const float* __restrict__ logits) {
    int b = threadIdx.x;
    if (b < NB) {
        float p[8];
        float mx = -1e30f;
        for (int e = 0; e < 8; e++) { p[e] = logits[b * 8 + e]; mx = fmaxf(mx, p[e]); }
        for (int e = 0; e < 8; e++) p[e] = __expf(p[e] - mx);
        int a1 = 0;
        for (int e = 1; e < 8; e++) if (p[e] > p[a1]) a1 = e;
        int a2 = (a1 == 0) ? 1 : 0;
        for (int e = 0; e < 8; e++) if (e != a1 && p[e] > p[a2]) a2 = e;
        float t = p[a1] + p[a2];
        g_texp[b * 3 + 0] = a1; g_twgt[b * 3 + 0] = p[a1] / t;
        g_texp[b * 3 + 1] = a2; g_twgt[b * 3 + 1] = p[a2] / t;
        g_texp[b * 3 + 2] = 8;  g_twgt[b * 3 + 2] = 1.0f;
    }
    __syncthreads();
    if (threadIdx.x == 0) {
        int pos = 0;
        for (int e = 0; e < NEXP; e++)
            for (int t = 0; t < NTASK; t++)
                if (g_texp[t] == e) g_tsched[pos++] = t;
    }
}

// ---------------- pack x: fp32 -> fp16 --------------------------------------
__global__ void k_pack_x(const float* __restrict__ x) {
    size_t i = (size_t)blockIdx.x * 256 + threadIdx.x;
    if (i < (size_t)NB * NS * NH)
        g_xs[i] = __float2half(x[i]);
}

// ---------------- transpose gate/up: [e][h][i] -> [e][i][h] fp16 -------------
__global__ void k_tr_gu(const float* __restrict__ sg, const float* __restrict__ shg,
                        const float* __restrict__ su, const float* __restrict__ shu) {
    __shared__ float tile[32][33];
    int z = blockIdx.z, which = z / NEXP, e = z % NEXP;
    size_t off = (size_t)e * NH * NI;
    const float* src;
    __half* dst;
    if (which == 0) { src = (e < 8) ? sg + off : shg; dst = g_gT + off; }
    else            { src = (e < 8) ? su + off : shu; dst = g_uT + off; }
    int i0 = blockIdx.x * 32, h0 = blockIdx.y * 32;
    int tx = threadIdx.x, ty = threadIdx.y;
#pragma unroll
    for (int k = 0; k < 4; k++)
        tile[ty + k * 8][tx] = src[(size_t)(h0 + ty + k * 8) * NI + i0 + tx];
    __syncthreads();
#pragma unroll
    for (int k = 0; k < 4; k++) {
        int ir = i0 + ty + k * 8;
        dst[(size_t)ir * NH + h0 + tx] = __float2half(tile[tx][ty + k * 8]);
    }
}

// ---------------- transpose down: [e][i][h] -> [e][h][i] fp16 ----------------
__global__ void k_tr_dn(const float* __restrict__ sd, const float* __restrict__ shd) {
    __shared__ float tile[32][33];
    int e = blockIdx.z;
    size_t off = (size_t)e * NI * NH;
    const float* src = (e < 8) ? sd + off : shd;
    __half* dst = g_dT + off;
    int h0 = blockIdx.x * 32, i0 = blockIdx.y * 32;
    int tx = threadIdx.x, ty = threadIdx.y;
#pragma unroll
    for (int k = 0; k < 4; k++)
        tile[ty + k * 8][tx] = src[(size_t)(i0 + ty + k * 8) * NH + h0 + tx];
    __syncthreads();
#pragma unroll
    for (int k = 0; k < 4; k++) {
        int hr = h0 + ty + k * 8;
        dst[(size_t)hr * NI + i0 + tx] = __float2half(tile[tx][ty + k * 8]);
    }
}

// ===========================================================================
// GEMM1: h = w * gelu(x@G) * (x@U)
//   CTA tile 128(M) x 64(N), dual output, BK=64, 3 cp.async stages,
//   256 threads. grid: task(96) x m(2) x n(64).  K-chunks: 16.
// SMEM rows 144B (64 fp16 + 16B pad; ldmatrix conflict-free: stride 9x16B).
// ===========================================================================
#define ROWB 144
#define G1_STAGE (256 * ROWB)                        // A(128)+BG(64)+BU(64)
#define G1_SMEM  (3 * G1_STAGE)                      // 110592
#define G1_CHUNKS 16

__device__ __forceinline__ void g1_load(uint32_t sbase, int stage, int tid,
                                        const __half* A,
                                        const __half* BG,
                                        const __half* BU) {
    uint32_t s = sbase + stage * G1_STAGE;
#pragma unroll
    for (int q = 0; q < 8; q++) {
        int t = tid + q * 256;                       // 0..2047
        if (t < 1024) {
            int r = t >> 3, j = t & 7;
            cp16(s + r * ROWB + j * 16, (const char*)(A + (size_t)r * NH) + j * 16);
        } else if (t < 1536) {
            int tt = t - 1024, r = tt >> 3, j = tt & 7;
            cp16(s + 128 * ROWB + r * ROWB + j * 16,
                 (const char*)(BG + (size_t)r * NH) + j * 16);
        } else {
            int tt = t - 1536, r = tt >> 3, j = tt & 7;
            cp16(s + 192 * ROWB + r * ROWB + j * 16,
                 (const char*)(BU + (size_t)r * NH) + j * 16);
        }
    }
}

__device__ __forceinline__ void g1_ptrs(int c, int batch, int e, int m0, int n0,
                                        const __half*& A,
                                        const __half*& BG,
                                        const __half*& BU) {
    A  = g_xs + ((size_t)batch * NS + m0) * NH + c * 64;
    BG = g_gT + ((size_t)e * NI + n0) * NH + c * 64;
    BU = g_uT + ((size_t)e * NI + n0) * NH + c * 64;
}

__global__ __launch_bounds__(256, 1) void k_gemm1() {
    extern __shared__ char smem[];
    const uint32_t sbase = smem_u32(smem);
    const int tid  = threadIdx.x;
    const int lane = tid & 31;
    const int wid  = tid >> 5;
    const int mb   = (wid >> 1) * 32;     // warp m-offset
    const int nb   = (wid & 1) * 32;      // warp n-offset

    int bid = blockIdx.x;
    int p   = bid >> 7;
    int m   = (bid >> 6) & 1;
    int n   = bid & 63;
    int task  = g_tsched[p];
    int batch = task / 3;
    int e     = g_texp[task];
    int m0 = m * 128, n0 = n * 64;

    float accg[2][4][4] = {}, accu[2][4][4] = {};

    const __half *A, *BG, *BU;
    g1_ptrs(0, batch, e, m0, n0, A, BG, BU);
    g1_load(sbase, 0, tid, A, BG, BU);
    CP_COMMIT();
    g1_ptrs(1, batch, e, m0, n0, A, BG, BU);
    g1_load(sbase, 1, tid, A, BG, BU);
    CP_COMMIT();

    const int rsel = lane & 15;
    const int ksel = (lane >> 4) & 1;

    for (int c = 0; c < G1_CHUNKS; c++) {
        CP_WAIT1();
        __syncthreads();
        {
            uint32_t sa = sbase + (c % 3) * G1_STAGE;
            uint32_t sg = sa + 128 * ROWB;
            uint32_t su = sa + 192 * ROWB;
#pragma unroll
            for (int k16 = 0; k16 < 4; k16++) {
                uint32_t kb = k16 * 32 + ksel * 16;
                uint32_t a[2][4];
#pragma unroll
                for (int mi = 0; mi < 2; mi++)
                    LDM4(a[mi][0], a[mi][1], a[mi][2], a[mi][3],
                         sa + (mb + mi * 16 + rsel) * ROWB + kb);
                uint32_t bg[4][2], bu[4][2];
#pragma unroll
                for (int bi = 0; bi < 2; bi++) {
                    uint32_t r0, r1, r2, r3;
                    LDM4(r0, r1, r2, r3, sg + (nb + bi * 16 + rsel) * ROWB + kb);
                    bg[bi * 2][0] = r0; bg[bi * 2][1] = r2;
                    bg[bi * 2 + 1][0] = r1; bg[bi * 2 + 1][1] = r3;
                    LDM4(r0, r1, r2, r3, su + (nb + bi * 16 + rsel) * ROWB + kb);
                    bu[bi * 2][0] = r0; bu[bi * 2][1] = r2;
                    bu[bi * 2 + 1][0] = r1; bu[bi * 2 + 1][1] = r3;
                }
#pragma unroll
                for (int mi = 0; mi < 2; mi++)
#pragma unroll
                    for (int ni = 0; ni < 4; ni++) {
                        MMA(accg[mi][ni], a[mi], bg[ni][0], bg[ni][1]);
                        MMA(accu[mi][ni], a[mi], bu[ni][0], bu[ni][1]);
                    }
            }
        }
        if (c + 2 < G1_CHUNKS) {
            g1_ptrs(c + 2, batch, e, m0, n0, A, BG, BU);
            g1_load(sbase, (c + 2) % 3, tid, A, BG, BU);
        }
        CP_COMMIT();
    }

    // epilogue: v = w * gelu(g) * u -> fp16 store
    const float wt = g_twgt[task];
#pragma unroll
    for (int mi = 0; mi < 2; mi++)
#pragma unroll
        for (int ni = 0; ni < 4; ni++)
#pragma unroll
            for (int rp = 0; rp < 4; rp += 2) {
                int mrow = m0 + mb + mi * 16 + (lane >> 2) + (rp ? 8 : 0);
                int ncol = n0 + nb + ni * 8 + (lane & 3) * 2;
                float v0 = wt * gelu_tanh(accg[mi][ni][rp])     * accu[mi][ni][rp];
                float v1 = wt * gelu_tanh(accg[mi][ni][rp + 1]) * accu[mi][ni][rp + 1];
                size_t idx = ((size_t)task * NS + mrow) * NI + ncol;
                *reinterpret_cast<__half2*>(&g_h[idx]) =
                    __halves2half2(__float2half(v0), __float2half(v1));
            }
}

// ===========================================================================
// GEMM2: out[batch] = sum over {3 tasks} of h @ D^T
//   CTA tile 128(M) x 128(N), warp 32x64, BK=64, 3 stages, 256 threads.
//   grid: batch(32) x m(2) x n(8).  K-chunks: 3 tasks x 64 = 192.
// ===========================================================================
#define G2_STAGE (256 * ROWB)                        // A(128)+B(128)
#define G2_SMEM  (3 * G2_STAGE)                      // 110592
#define G2_CHUNKS 192

__device__ __forceinline__ void g2_load(uint32_t sbase, int stage, int tid,
                                        const __half* A,
                                        const __half* B) {
    uint32_t s = sbase + stage * G2_STAGE;
#pragma unroll
    for (int q = 0; q < 8; q++) {
        int t = tid + q * 256;                       // 0..2047
        if (t < 1024) {
            int r = t >> 3, j = t & 7;
            cp16(s + r * ROWB + j * 16, (const char*)(A + (size_t)r * NI) + j * 16);
        } else {
            int tt = t - 1024, r = tt >> 3, j = tt & 7;
            cp16(s + 128 * ROWB + r * ROWB + j * 16,
                 (const char*)(B + (size_t)r * NI) + j * 16);
        }
    }
}

__device__ __forceinline__ void g2_ptrs(int c, int batch, int m0, int n0,
                                        const __half*& A,
                                        const __half*& B) {
    int ti = c >> 6;            // 0..2
    int kc = c & 63;
    int task = batch * 3 + ti;
    int e    = g_texp[task];
    A = g_h  + ((size_t)task * NS + m0) * NI + kc * 64;
    B = g_dT + ((size_t)e * NH + n0) * NI + kc * 64;
}

__global__ __launch_bounds__(256, 1) void k_gemm2(float* __restrict__ out) {
    extern __shared__ char smem[];
    const uint32_t sbase = smem_u32(smem);
    const int tid  = threadIdx.x;
    const int lane = tid & 31;
    const int wid  = tid >> 5;
    const int mb   = (wid >> 1) * 32;
    const int nb   = (wid & 1) * 64;

    int bid   = blockIdx.x;
    int batch = bid >> 4;
    int m     = (bid >> 3) & 1;
    int n     = bid & 7;
    int m0 = m * 128, n0 = n * 128;

    float acc[2][8][4] = {};

    const __half *A, *B;
    g2_ptrs(0, batch, m0, n0, A, B);
    g2_load(sbase, 0, tid, A, B);
    CP_COMMIT();
    g2_ptrs(1, batch, m0, n0, A, B);
    g2_load(sbase, 1, tid, A, B);
    CP_COMMIT();

    const int rsel = lane & 15;
    const int ksel = (lane >> 4) & 1;

    for (int c = 0; c < G2_CHUNKS; c++) {
        CP_WAIT1();
        __syncthreads();
        {
            uint32_t sa = sbase + (c % 3) * G2_STAGE;
            uint32_t sb = sa + 128 * ROWB;
#pragma unroll
            for (int k16 = 0; k16 < 4; k16++) {
                uint32_t kb = k16 * 32 + ksel * 16;
                uint32_t a[2][4];
#pragma unroll
                for (int mi = 0; mi < 2; mi++)
                    LDM4(a[mi][0], a[mi][1], a[mi][2], a[mi][3],
                         sa + (mb + mi * 16 + rsel) * ROWB + kb);
                uint32_t bf[8][2];
#pragma unroll
                for (int bi = 0; bi < 4; bi++) {
                    uint32_t r0, r1, r2, r3;
                    LDM4(r0, r1, r2, r3, sb + (nb + bi * 16 + rsel) * ROWB + kb);
                    bf[bi * 2][0] = r0; bf[bi * 2][1] = r2;
                    bf[bi * 2 + 1][0] = r1; bf[bi * 2 + 1][1] = r3;
                }
#pragma unroll
                for (int mi = 0; mi < 2; mi++)
#pragma unroll
                    for (int ni = 0; ni < 8; ni++)
                        MMA(acc[mi][ni], a[mi], bf[ni][0], bf[ni][1]);
            }
        }
        if (c + 2 < G2_CHUNKS) {
            g2_ptrs(c + 2, batch, m0, n0, A, B);
            g2_load(sbase, (c + 2) % 3, tid, A, B);
        }
        CP_COMMIT();
    }

    // epilogue: fp32 store (covers every output element exactly once)
#pragma unroll
    for (int mi = 0; mi < 2; mi++)
#pragma unroll
        for (int ni = 0; ni < 8; ni++)
#pragma unroll
            for (int rp = 0; rp < 4; rp += 2) {
                int mrow = m0 + mb + mi * 16 + (lane >> 2) + (rp ? 8 : 0);
                int ncol = n0 + nb + ni * 8 + (lane & 3) * 2;
                float2 v = make_float2(acc[mi][ni][rp], acc[mi][ni][rp + 1]);
                *reinterpret_cast<float2*>(
                    &out[((size_t)batch * NS + mrow) * NH + ncol]) = v;
            }
}

// ---------------- launch -----------------------------------------------------
extern "C" void kernel_launch(void* const* d_in, const int* in_sizes, int n_in,
                              void* d_out, int out_size) {
    const float* x      = (const float*)d_in[0];
    const float* logits = (const float*)d_in[1];
    const float* sg     = (const float*)d_in[2];
    const float* su     = (const float*)d_in[3];
    const float* sd     = (const float*)d_in[4];
    const float* shg    = (const float*)d_in[5];
    const float* shu    = (const float*)d_in[6];
    const float* shd    = (const float*)d_in[7];
    float* out = (float*)d_out;

    (void)cudaFuncSetAttribute(k_gemm1, cudaFuncAttributeMaxDynamicSharedMemorySize, G1_SMEM);
    (void)cudaFuncSetAttribute(k_gemm2, cudaFuncAttributeMaxDynamicSharedMemorySize, G2_SMEM);

    k_route<<<1, 128>>>(logits);
    k_pack_x<<<(NB * NS * NH) / 256, 256>>>(x);
    k_tr_gu<<<dim3(NI / 32, NH / 32, 2 * NEXP), dim3(32, 8)>>>(sg, shg, su, shu);
    k_tr_dn<<<dim3(NH / 32, NI / 32, NEXP), dim3(32, 8)>>>(sd, shd);
    k_gemm1<<<NTASK * 2 * 64, 256, G1_SMEM>>>();
    k_gemm2<<<NB * 2 * 8, 256, G2_SMEM>>>(out);
}